// round 3
// baseline (speedup 1.0000x reference)
#include <cuda_runtime.h>
#include <math.h>

#define BB    32
#define TT    128
#define INDIM 512
#define OUTDIM 512
#define NSLOT 128
#define WD    64
#define RH    4
#define HID   512
#define IFACE 471
#define ZCOLS 2048
#define EPSF  1e-6f

// ---------------- persistent device state ----------------
__device__ float g_h[2][BB*HID];
__device__ float g_c[BB*HID];
__device__ float g_M[BB*NSLOT*WD];
__device__ float g_usage[BB*NSLOT];
__device__ float g_link[BB*NSLOT*NSLOT];
__device__ float g_prec[BB*NSLOT];
__device__ float g_ww[BB*NSLOT];
__device__ float g_wr[BB*RH*NSLOT];
__device__ float g_reads[BB*RH*WD];
__device__ float g_zpart[5][BB*ZCOLS];   // lstm split-K partials
__device__ float g_vpart[4][BB*480];     // iface split-K partials (padded cols)

__device__ __forceinline__ float sigm(float x){ return 1.f/(1.f+expf(-x)); }
__device__ __forceinline__ float softplusf(float x){
    return (x > 0.f) ? x + log1pf(expf(-x)) : log1pf(expf(x));
}

// ---------------- init ----------------
__global__ void k_init()
{
    int i0 = blockIdx.x*blockDim.x + threadIdx.x;
    int st = gridDim.x*blockDim.x;
    for (int i = i0; i < 2*BB*HID; i += st) ((float*)g_h)[i] = 0.f;
    for (int i = i0; i < BB*HID; i += st) g_c[i] = 0.f;
    for (int i = i0; i < BB*NSLOT*WD; i += st) g_M[i] = 0.f;
    for (int i = i0; i < BB*NSLOT; i += st) { g_usage[i]=0.f; g_prec[i]=0.f; g_ww[i]=0.f; }
    for (int i = i0; i < BB*NSLOT*NSLOT; i += st) g_link[i] = 0.f;
    for (int i = i0; i < BB*RH*NSLOT; i += st) g_wr[i] = 0.f;
    for (int i = i0; i < BB*RH*WD; i += st) g_reads[i] = 0.f;
}

// ---------------- output GEMM (shared device fn) ----------------
// out[b, tcur, :] = [reads(256), h_n(512)] @ W_out + b_out
// one block per 16-col tile (ct in 0..31), 256 threads
__device__ void out_gemm_device(int ct, int tcur, const float* __restrict__ hn,
                                const float* __restrict__ Wout, const float* __restrict__ bout,
                                float* __restrict__ out, float* sA, float* sB)
{
    int tid = threadIdx.x;
    int tx = tid & 15, ty = tid >> 4;
    float acc0 = 0.f, acc1 = 0.f;
    for (int kt = 0; kt < 768; kt += 32) {
        #pragma unroll
        for (int r = 0; r < 4; r++) {
            int idx = tid + r*256;
            int b = idx >> 5, kk = idx & 31;
            int kg = kt + kk;
            float v = (kg < 256) ? g_reads[b*256 + kg] : hn[b*HID + (kg - 256)];
            sA[kk*34 + b] = v;
        }
        #pragma unroll
        for (int r = 0; r < 2; r++) {
            int idx = tid + r*256;
            int kk = idx >> 4, c = idx & 15;
            sB[kk*16 + c] = Wout[(kt + kk)*OUTDIM + ct*16 + c];
        }
        __syncthreads();
        #pragma unroll
        for (int kk = 0; kk < 32; kk++) {
            float a0 = sA[kk*34 + 2*ty], a1 = sA[kk*34 + 2*ty + 1];
            float w = sB[kk*16 + tx];
            acc0 += a0*w; acc1 += a1*w;
        }
        __syncthreads();
    }
    int col = ct*16 + tx;
    float bv = bout[col];
    out[((2*ty)  *TT + tcur)*OUTDIM + col] = acc0 + bv;
    out[((2*ty+1)*TT + tcur)*OUTDIM + col] = acc1 + bv;
}

// ---------------- step A: LSTM GEMM partials + fused prev-step out GEMM ------
// blocks 0..159: 32 col-tiles (x64 cols) x 5 K-splits of 256 -> g_zpart
// blocks 160..191: out gemm for step t-1
__global__ void k_step_a(const float* __restrict__ xseq,
                         const float* __restrict__ Wx,
                         const float* __restrict__ Wh,
                         const float* __restrict__ Wout,
                         const float* __restrict__ bout,
                         float* __restrict__ out, int t)
{
    __shared__ __align__(16) float sh[32*34 + 32*64];
    int p = t & 1;
    if (blockIdx.x < 160) {
        float* sA = sh;            // [32][34]  (k x b)
        float* sB = sh + 32*34;    // [32][64]  (k x c)
        int ct = blockIdx.x / 5;
        int s  = blockIdx.x % 5;
        int tid = threadIdx.x;
        int tx = tid & 15, ty = tid >> 4;
        float acc[2][4] = {{0,0,0,0},{0,0,0,0}};
        const float* hprev = g_h[p];
        const float* W = (s >= 3) ? Wh : Wx;
        int rowoff = (s >= 3) ? 768 : 0;
        int kbase = s * 256;
        for (int kt = 0; kt < 256; kt += 32) {
            #pragma unroll
            for (int r = 0; r < 4; r++) {
                int idx = tid + r*256;
                int b = idx >> 5, kk = idx & 31;
                int kg = kbase + kt + kk;
                float v;
                if (s < 2)       v = xseq[(b*TT + t)*INDIM + kg];
                else if (s == 2) v = g_reads[b*256 + (kg - 512)];
                else             v = hprev[b*HID + (kg - 768)];
                sA[kk*34 + b] = v;
            }
            #pragma unroll
            for (int r = 0; r < 8; r++) {
                int idx = tid + r*256;
                int kk = idx >> 6, c = idx & 63;
                int kg = kbase + kt + kk;
                sB[kk*64 + c] = W[(kg - rowoff)*ZCOLS + ct*64 + c];
            }
            __syncthreads();
            #pragma unroll
            for (int kk = 0; kk < 32; kk++) {
                float a0 = sA[kk*34 + 2*ty], a1 = sA[kk*34 + 2*ty + 1];
                float4 w = *(const float4*)&sB[kk*64 + tx*4];
                acc[0][0] += a0*w.x; acc[0][1] += a0*w.y; acc[0][2] += a0*w.z; acc[0][3] += a0*w.w;
                acc[1][0] += a1*w.x; acc[1][1] += a1*w.y; acc[1][2] += a1*w.z; acc[1][3] += a1*w.w;
            }
            __syncthreads();
        }
        float* zp = g_zpart[s];
        int col0 = ct*64 + tx*4;
        #pragma unroll
        for (int i = 0; i < 4; i++) {
            zp[(2*ty)  *ZCOLS + col0 + i] = acc[0][i];
            zp[(2*ty+1)*ZCOLS + col0 + i] = acc[1][i];
        }
    } else {
        if (t == 0) return;
        // h_n(t-1) is in g_h[p]; g_reads still holds reads(t-1)
        out_gemm_device(blockIdx.x - 160, t - 1, g_h[p], Wout, bout, out, sh, sh + 32*34);
    }
}

// ---------------- step B: reduce partials + LSTM elementwise ----------------
__global__ void k_step_b(const float* __restrict__ b_lstm, int t)
{
    int p = t & 1;
    int g = blockIdx.x*256 + threadIdx.x;   // 0..16383
    int b = g >> 9, j = g & 511;
    float zi = b_lstm[j], zf = b_lstm[512+j], zg = b_lstm[1024+j], zo = b_lstm[1536+j];
    #pragma unroll
    for (int s = 0; s < 5; s++) {
        const float* zp = g_zpart[s] + b*ZCOLS;
        zi += zp[j]; zf += zp[512+j]; zg += zp[1024+j]; zo += zp[1536+j];
    }
    float c  = g_c[b*HID + j];
    float ig = sigm(zi), fg = sigm(zf), gg = tanhf(zg), og = sigm(zo);
    float cn = fg*c + ig*gg;
    float hn = og*tanhf(cn);
    g_c[b*HID + j] = cn;
    g_h[p^1][b*HID + j] = hn;
}

// ---------------- step C: iface GEMM partials ----------------
// 15 col-tiles (x32 cols) x 4 K-splits of 128 -> g_vpart
__global__ void k_step_c(const float* __restrict__ Wif, int t)
{
    __shared__ __align__(16) float sA[32*34];
    __shared__ __align__(16) float sB[32*32];
    const float* hn = g_h[(t & 1) ^ 1];
    int ct = blockIdx.x / 4;
    int s  = blockIdx.x % 4;
    int tid = threadIdx.x;
    int tx = tid & 7, ty = tid >> 3;   // ty = batch row
    float acc[4] = {0,0,0,0};
    int kbase = s*128;
    for (int kt = 0; kt < 128; kt += 32) {
        #pragma unroll
        for (int r = 0; r < 4; r++) {
            int idx = tid + r*256;
            int b = idx >> 5, kk = idx & 31;
            sA[kk*34 + b] = hn[b*HID + kbase + kt + kk];
        }
        #pragma unroll
        for (int r = 0; r < 4; r++) {
            int idx = tid + r*256;
            int kk = idx >> 5, c = idx & 31;
            int col = ct*32 + c;
            sB[kk*32 + c] = (col < IFACE) ? Wif[(kbase+kt+kk)*IFACE + col] : 0.f;
        }
        __syncthreads();
        #pragma unroll
        for (int kk = 0; kk < 32; kk++) {
            float a = sA[kk*34 + ty];
            float4 w = *(const float4*)&sB[kk*32 + tx*4];
            acc[0] += a*w.x; acc[1] += a*w.y; acc[2] += a*w.z; acc[3] += a*w.w;
        }
        __syncthreads();
    }
    float* vp = g_vpart[s];
    #pragma unroll
    for (int i = 0; i < 4; i++)
        vp[ty*480 + ct*32 + tx*4 + i] = acc[i];
}

// ---------------- step D: DNC memory machinery, one block (128 thr) per batch
#define MEM_SMEM_FLOATS (8320 + 16512 + 480 + 64 + 5*512 + 8*128 + 32 + 128)
#define MEM_SMEM_BYTES  (MEM_SMEM_FLOATS*4)

__global__ void k_memory(const float* __restrict__ b_iface)
{
    extern __shared__ float sm[];
    const int b = blockIdx.x;
    const int tid = threadIdx.x;      // 0..127, tid == memory slot n
    float* sM  = sm;                  // 128 x 65 (padded)
    float* sL  = sM + 8320;           // 128 x 129 (padded)
    float* sv  = sL + 16512;          // 480 (471 used)
    float* ers = sv + 480;            // 64
    float* wro = ers + 64;            // 512 old wr
    float* fwv = wro + 512;           // 512
    float* bwv = fwv + 512;           // 512
    float* crs = bwv + 512;           // 512
    float* wrn = crs + 512;           // 512
    float* u_s = wrn + 512;           // 128  usage_n
    float* so  = u_s + 128;           // 128  sorted -> cumprod
    float* su  = so + 128;            // 128  sorted copy
    float* a_s = su + 128;            // 128  a_sorted
    float* cw  = a_s + 128;           // 128  write content w
    float* ww  = cw + 128;            // 128  ww_n
    float* pr  = ww + 128;            // 128  old precedence
    float* red = pr + 128;            // 128  reduction buffer
    float* scal= red + 128;           // 32
    int* irank = (int*)(scal + 32);   // 128

    float uo  = g_usage[b*128 + tid];
    float wwo = g_ww[b*128 + tid];

    for (int j = tid; j < IFACE; j += 128) {
        float v = b_iface[j];
        #pragma unroll
        for (int s = 0; s < 4; s++) v += g_vpart[s][b*480 + j];
        sv[j] = v;
    }
    for (int idx = tid; idx < 8192; idx += 128)
        sM[(idx>>6)*65 + (idx&63)] = g_M[b*8192 + idx];
    for (int idx = tid; idx < 16384; idx += 128)
        sL[(idx>>7)*129 + (idx&127)] = g_link[b*16384 + idx];
    pr[tid] = g_prec[b*128 + tid];
    for (int idx = tid; idx < 512; idx += 128) wro[idx] = g_wr[b*512 + idx];
    __syncthreads();

    // ---- parse interface ----
    if (tid < 64) ers[tid] = sigm(sv[325+tid]);
    if (tid < 4) {
        scal[4+tid] = 1.f + softplusf(sv[256+tid]);        // read beta
        scal[8+tid] = sigm(sv[453+tid]);                   // free gate
        float m0=sv[459+3*tid], m1=sv[460+3*tid], m2=sv[461+3*tid];
        float mx=fmaxf(m0,fmaxf(m1,m2));
        float e0=expf(m0-mx), e1=expf(m1-mx), e2=expf(m2-mx);
        float si=e0+e1+e2;
        scal[16+3*tid]=e0/si; scal[17+3*tid]=e1/si; scal[18+3*tid]=e2/si;
        float s2=0.f;
        for (int w=0;w<64;w++){ float k=sv[tid*64+w]; s2+=k*k; }
        scal[12+tid]=sqrtf(s2)+EPSF;                       // ||read key r||
    }
    if (tid == 4) {
        scal[0] = 1.f + softplusf(sv[324]);                // write beta
        float s2=0.f;
        for (int w=0;w<64;w++){ float k=sv[260+w]; s2+=k*k; }
        scal[3] = sqrtf(s2)+EPSF;                          // ||write key||
    }
    if (tid == 5) scal[1] = sigm(sv[457]);                 // alloc gate
    if (tid == 6) scal[2] = sigm(sv[458]);                 // write gate
    __syncthreads();

    // ---- usage ----
    {
        float ret = 1.f;
        #pragma unroll
        for (int r = 0; r < 4; r++) ret *= (1.f - scal[8+r]*wro[r*128+tid]);
        float un = (uo + wwo - uo*wwo) * ret;
        u_s[tid] = un;
        g_usage[b*128 + tid] = un;
    }
    // ---- write content weighting on OLD M ----
    {
        float d=0.f, n2=0.f;
        for (int w=0; w<64; w++){ float m=sM[tid*65+w]; d += m*sv[260+w]; n2 += m*m; }
        cw[tid] = scal[0] * (d / ((sqrtf(n2)+EPSF)*scal[3]));
    }
    red[tid] = cw[tid];
    __syncthreads();
    for (int st=64; st>=1; st>>=1){ if (tid<st) red[tid]=fmaxf(red[tid],red[tid+st]); __syncthreads(); }
    float wmax = red[0]; __syncthreads();
    float we = expf(cw[tid]-wmax);
    red[tid] = we; __syncthreads();
    for (int st=64; st>=1; st>>=1){ if (tid<st) red[tid]+=red[tid+st]; __syncthreads(); }
    float wsum = red[0]; __syncthreads();
    cw[tid] = we / wsum;

    // ---- allocation: stable rank-sort + cumprod scan ----
    {
        float un = u_s[tid];
        int rk_ = 0;
        for (int m=0; m<128; m++){
            float um = u_s[m];
            rk_ += ((um<un) || (um==un && m<tid)) ? 1 : 0;
        }
        irank[tid] = rk_;
        so[rk_] = un; su[rk_] = un;
    }
    __syncthreads();
    for (int d=1; d<128; d<<=1) {
        float tv = (tid>=d) ? so[tid-d] : 1.f;
        __syncthreads();
        so[tid] *= tv;
        __syncthreads();
    }
    {
        float cpe = (tid==0) ? 1.f : so[tid-1];
        a_s[tid] = (1.f - su[tid]) * cpe;
    }
    __syncthreads();
    {
        float a = a_s[irank[tid]];
        float ag = scal[1], wg = scal[2];
        float wwn = wg * (ag*a + (1.f-ag)*cw[tid]);
        ww[tid] = wwn;
        g_ww[b*128+tid] = wwn;
    }
    __syncthreads();

    // ---- ww sum for precedence ----
    red[tid] = ww[tid]; __syncthreads();
    for (int st=64; st>=1; st>>=1){ if (tid<st) red[tid]+=red[tid+st]; __syncthreads(); }
    float wwsum = red[0]; __syncthreads();

    // ---- memory write ----
    for (int idx = tid; idx < 8192; idx += 128) {
        int n = idx>>6, w = idx&63;
        float m = sM[n*65+w];
        m = m*(1.f - ww[n]*ers[w]) + ww[n]*sv[389+w];
        sM[n*65+w] = m;
        g_M[b*8192 + idx] = m;
    }
    // ---- link update (row i = tid), old prec ----
    {
        float wwi = ww[tid];
        for (int j = 0; j < 128; j++) {
            float l = sL[tid*129+j];
            l = (1.f - wwi - ww[j])*l + wwi*pr[j];
            if (j == tid) l = 0.f;
            sL[tid*129+j] = l;
            g_link[b*16384 + tid*128 + j] = l;
        }
        g_prec[b*128+tid] = (1.f - wwsum)*pr[tid] + wwi;
    }
    __syncthreads();

    // ---- forward / backward weights ----
    #pragma unroll
    for (int r = 0; r < 4; r++) {
        float f=0.f, bk=0.f;
        for (int j = 0; j < 128; j++) {
            float wrj = wro[r*128+j];
            f  += sL[tid*129+j]*wrj;
            bk += sL[j*129+tid]*wrj;
        }
        fwv[r*128+tid] = f;
        bwv[r*128+tid] = bk;
    }
    // ---- read content on NEW M ----
    {
        float n2=0.f;
        for (int w=0;w<64;w++){ float m=sM[tid*65+w]; n2+=m*m; }
        float inv = 1.f/(sqrtf(n2)+EPSF);
        #pragma unroll
        for (int r=0;r<4;r++){
            float d=0.f;
            for (int w=0;w<64;w++) d += sM[tid*65+w]*sv[r*64+w];
            crs[r*128+tid] = scal[4+r]*d*inv/scal[12+r];
        }
    }
    __syncthreads();
    for (int r=0;r<4;r++){
        red[tid] = crs[r*128+tid]; __syncthreads();
        for (int st=64; st>=1; st>>=1){ if (tid<st) red[tid]=fmaxf(red[tid],red[tid+st]); __syncthreads(); }
        float mx = red[0]; __syncthreads();
        float e = expf(crs[r*128+tid]-mx);
        red[tid]=e; __syncthreads();
        for (int st=64; st>=1; st>>=1){ if (tid<st) red[tid]+=red[tid+st]; __syncthreads(); }
        float s = red[0]; __syncthreads();
        crs[r*128+tid] = e/s;
    }
    // ---- read weights ----
    #pragma unroll
    for (int r=0;r<4;r++){
        float w = scal[16+3*r]*bwv[r*128+tid] + scal[17+3*r]*crs[r*128+tid] + scal[18+3*r]*fwv[r*128+tid];
        wrn[r*128+tid] = w;
        g_wr[b*512 + r*128 + tid] = w;
    }
    __syncthreads();
    // ---- reads ----
    for (int idx = tid; idx < 256; idx += 128) {
        int r = idx>>6, w = idx&63;
        float s = 0.f;
        for (int n=0;n<128;n++) s += wrn[r*128+n]*sM[n*65+w];
        g_reads[b*256 + idx] = s;
    }
}

// ---------------- final out GEMM (t = 127) ----------------
__global__ void k_out_final(const float* __restrict__ Wout,
                            const float* __restrict__ bout,
                            float* __restrict__ out)
{
    __shared__ __align__(16) float sh[32*34 + 32*16];
    // step 127: h_n in g_h[(127&1)^1] == g_h[0], reads(127) in g_reads
    out_gemm_device(blockIdx.x, 127, g_h[0], Wout, bout, out, sh, sh + 32*34);
}

extern "C" void kernel_launch(void* const* d_in, const int* in_sizes, int n_in,
                              void* d_out, int out_size)
{
    const float* xseq = (const float*)d_in[0];
    const float* Wx   = (const float*)d_in[1];
    const float* Wh   = (const float*)d_in[2];
    const float* bl   = (const float*)d_in[3];
    const float* Wif  = (const float*)d_in[4];
    const float* bif  = (const float*)d_in[5];
    const float* Wout = (const float*)d_in[6];
    const float* bout = (const float*)d_in[7];
    float* out = (float*)d_out;

    cudaFuncSetAttribute(k_memory, cudaFuncAttributeMaxDynamicSharedMemorySize, MEM_SMEM_BYTES);

    k_init<<<64, 256>>>();
    for (int t = 0; t < TT; t++) {
        k_step_a<<<192, 256>>>(xseq, Wx, Wh, Wout, bout, out, t);
        k_step_b<<<64, 256>>>(bl, t);
        k_step_c<<<60, 256>>>(Wif, t);
        k_memory<<<32, 128, MEM_SMEM_BYTES>>>(bif);
    }
    k_out_final<<<32, 256>>>(Wout, bout, out);
}

// round 4
// speedup vs baseline: 1.0598x; 1.0598x over previous
#include <cuda_runtime.h>
#include <math.h>

#define BB    32
#define TT    128
#define OUTDIM 512
#define HID   512
#define IFACE 471
#define EPSF  1e-6f
#define NBLK  128
#define NTHR  512

// ---------------- smem layout (floats) ----------------
#define SM_M      0        // 128x65            (persistent, blocks<32)
#define SM_L      8320     // 128x129           (persistent)
#define SM_WRP    24832    // 512  wr           (persistent)
#define SM_USAGE  25344    // 128               (persistent)
#define SM_PREC   25472    // 128               (persistent)
#define SM_WW     25600    // 128  old ww       (persistent)
#define SM_STAGE  25728    // 4 x 32x65 = 8320  (GEMM A staging)
#define SM_ZBUF   34048    // 2048              (split partials)
#define SM_SV     36096    // 480
#define SM_ERS    36576    // 64
#define SM_FWV    36640    // 512
#define SM_BWV    37152    // 512
#define SM_CRS    37664    // 512
#define SM_WRN    38176    // 512
#define SM_US     38688    // 128
#define SM_SO     38816    // 128
#define SM_SU     38944    // 128
#define SM_AS     39072    // 128
#define SM_CW     39200    // 128
#define SM_WWN    39328    // 128
#define SM_RED    39456    // 4x128
#define SM_SCAL   39968    // 32
#define SM_IRANK  40000    // 128 (int)
#define SM_TOTAL  40128
#define SMEM_BYTES (SM_TOTAL*4)

// ---------------- device globals ----------------
__device__ float g_h[2][BB*HID];
__device__ float g_reads[BB*256];
__device__ float g_v[BB*480];
__device__ unsigned g_count;   // monotonic barrier counter (never reset)

__device__ __forceinline__ float sigm(float x){ return 1.f/(1.f+expf(-x)); }
__device__ __forceinline__ float softplusf(float x){
    return (x>0.f) ? x+log1pf(expf(-x)) : log1pf(expf(x));
}

// grid-wide barrier: generation counting, replay-safe (no reset), wrap-safe.
__device__ __forceinline__ void gsync() {
    __syncthreads();
    if (threadIdx.x == 0) {
        __threadfence();
        unsigned v = atomicAdd(&g_count, 1u);
        unsigned target = v - (v & (NBLK-1u)) + NBLK;   // end of this generation
        while ((int)(*(volatile unsigned*)&g_count - target) < 0) { }
        __threadfence();   // gpu-scope fence -> L1 invalidate (CCTL.IVALL)
    }
    __syncthreads();
}

// named barrier over one 128-thread split (warps 4s..4s+3 are contiguous)
__device__ __forceinline__ void barsplit(int s){
    asm volatile("bar.sync %0, %1;" :: "r"(s+1), "r"(128) : "memory");
}

// ---------------- out GEMM: out[:, tout, bq*4..+4) = [reads, hsrc] @ Wout + bout
__device__ __forceinline__ void out_gemm(const float* __restrict__ Wout,
                                         const float* __restrict__ bout,
                                         float* __restrict__ out,
                                         const float* __restrict__ hsrc,
                                         int tout, int bq, int tid,
                                         float* stg, float* zb)
{
    const int s = tid >> 7, u = tid & 127, ub = u & 31, uc = u >> 5;
    float oacc = 0.f;
    const int ocol = bq*4 + uc;
    for (int ch = 0; ch < 3; ch++) {
        int k0 = s*192 + ch*64;
        for (int l = u; l < 2048; l += 128) {
            int brow = l >> 6, kc = l & 63;
            int k = k0 + kc;
            stg[brow*65 + kc] = (k < 256) ? g_reads[brow*256 + k]
                                          : hsrc[brow*512 + (k - 256)];
        }
        barsplit(s);
        const float* Wb = Wout + (size_t)k0*OUTDIM + ocol;
        #pragma unroll 8
        for (int kc = 0; kc < 64; kc++)
            oacc += stg[ub*65 + kc] * Wb[(size_t)kc*OUTDIM];
        barsplit(s);
    }
    zb[(s*4 + uc)*32 + ub] = oacc;
    __syncthreads();
    if (tid < 128) {
        int b = tid & 31, co = tid >> 5;
        float o = bout[bq*4 + co];
        #pragma unroll
        for (int ss = 0; ss < 4; ss++) o += zb[(ss*4 + co)*32 + b];
        out[((size_t)b*TT + tout)*OUTDIM + bq*4 + co] = o;
    }
    __syncthreads();
}

// ---------------- the whole DNC in one persistent kernel ----------------
__global__ void __launch_bounds__(NTHR, 1)
dnc_kernel(const float* __restrict__ xseq, const float* __restrict__ Wx,
           const float* __restrict__ Wh,   const float* __restrict__ bl,
           const float* __restrict__ Wif,  const float* __restrict__ bif,
           const float* __restrict__ Wout, const float* __restrict__ bout,
           float* __restrict__ out)
{
    extern __shared__ float sm[];
    const int tid = threadIdx.x;
    const int bq  = blockIdx.x;
    const int s   = tid >> 7;      // K-split 0..3
    const int u   = tid & 127;
    const int ub  = u & 31;        // batch row
    const int uc  = u >> 5;        // 0..3: gate (LSTM) / col-in-quad (out/iface)

    float* stg = sm + SM_STAGE + s*2080;   // this split's A stage: 32x65
    float* zb  = sm + SM_ZBUF;

    // ---------- init ----------
    for (int i = bq*NTHR + tid; i < BB*HID; i += NBLK*NTHR) g_h[0][i] = 0.f;
    for (int i = bq*NTHR + tid; i < BB*256; i += NBLK*NTHR) g_reads[i] = 0.f;
    if (bq < 32)
        for (int i = tid; i < SM_STAGE; i += NTHR) sm[i] = 0.f;   // persistent state
    float c_reg = 0.f;   // c for (b=tid&31, j=bq*4+(tid>>5)) when tid<128
    gsync();

    for (int t = 0; t < TT; t++) {
        const int p = t & 1;
        const float* hprev = g_h[p];
        float* hnew = g_h[p^1];

        // ================= phase A: LSTM z + gates + h; fused out(t-1) ======
        {
            float a0=0.f, a1=0.f, a2=0.f, a3=0.f;
            const int colbase = uc*512 + bq*4;
            for (int ch = 0; ch < 5; ch++) {
                int k0 = s*320 + ch*64;
                for (int l = u; l < 2048; l += 128) {
                    int brow = l >> 6, kc = l & 63;
                    int k = k0 + kc;
                    float vA;
                    if (k < 512)      vA = xseq[((size_t)brow*TT + t)*512 + k];
                    else if (k < 768) vA = g_reads[brow*256 + (k-512)];
                    else              vA = hprev[brow*512 + (k-768)];
                    stg[brow*65 + kc] = vA;
                }
                barsplit(s);
                const float* Wb = (k0 < 768) ? (Wx + (size_t)k0*2048 + colbase)
                                             : (Wh + (size_t)(k0-768)*2048 + colbase);
                #pragma unroll 8
                for (int kc = 0; kc < 64; kc++) {
                    float4 w = *(const float4*)(Wb + (size_t)kc*2048);
                    float a = stg[ub*65 + kc];
                    a0 += a*w.x; a1 += a*w.y; a2 += a*w.z; a3 += a*w.w;
                }
                barsplit(s);
            }
            zb[(s*16 + uc*4 + 0)*32 + ub] = a0;
            zb[(s*16 + uc*4 + 1)*32 + ub] = a1;
            zb[(s*16 + uc*4 + 2)*32 + ub] = a2;
            zb[(s*16 + uc*4 + 3)*32 + ub] = a3;
            __syncthreads();
            if (tid < 128) {
                int b = tid & 31, jj = tid >> 5;
                int j = bq*4 + jj;
                float z[4];
                #pragma unroll
                for (int g = 0; g < 4; g++) {
                    float zz = bl[g*512 + j];
                    #pragma unroll
                    for (int ss = 0; ss < 4; ss++) zz += zb[(ss*16 + g*4 + jj)*32 + b];
                    z[g] = zz;
                }
                float ig = sigm(z[0]), fg = sigm(z[1]);
                float gg = tanhf(z[2]), og = sigm(z[3]);
                c_reg = fg*c_reg + ig*gg;
                hnew[b*512 + j] = og * tanhf(c_reg);
            }
            __syncthreads();
            if (t > 0)
                out_gemm(Wout, bout, out, hprev, t-1, bq, tid, stg, zb);
        }
        gsync();

        // ================= phase C: iface v = h_n @ W_iface + b_iface =======
        {
            const int col = bq*4 + uc;
            float vacc = 0.f;
            for (int ch = 0; ch < 2; ch++) {
                int k0 = s*128 + ch*64;
                for (int l = u; l < 2048; l += 128) {
                    int brow = l >> 6, kc = l & 63;
                    stg[brow*65 + kc] = hnew[brow*512 + k0 + kc];
                }
                barsplit(s);
                if (col < IFACE) {
                    const float* Wb = Wif + (size_t)k0*IFACE + col;
                    #pragma unroll 8
                    for (int kc = 0; kc < 64; kc++)
                        vacc += stg[ub*65 + kc] * Wb[(size_t)kc*IFACE];
                }
                barsplit(s);
            }
            zb[(s*4 + uc)*32 + ub] = vacc;
            __syncthreads();
            if (tid < 128) {
                int b = tid & 31, co = tid >> 5;
                int col2 = bq*4 + co;
                if (col2 < IFACE) {
                    float vv = bif[col2];
                    #pragma unroll
                    for (int ss = 0; ss < 4; ss++) vv += zb[(ss*4 + co)*32 + b];
                    g_v[b*480 + col2] = vv;
                }
            }
        }
        gsync();

        // ================= phase D: memory machinery (blocks 0..31) =========
        if (bq < 32) {
            const int b = bq;
            float* sM  = sm + SM_M;    float* sL  = sm + SM_L;
            float* sWr = sm + SM_WRP;  float* sU  = sm + SM_USAGE;
            float* sP  = sm + SM_PREC; float* sW2 = sm + SM_WW;
            float* sv  = sm + SM_SV;   float* ers = sm + SM_ERS;
            float* fwv = sm + SM_FWV;  float* bwv = sm + SM_BWV;
            float* crs = sm + SM_CRS;  float* wrn = sm + SM_WRN;
            float* u_s = sm + SM_US;   float* so  = sm + SM_SO;
            float* su  = sm + SM_SU;   float* a_s = sm + SM_AS;
            float* cw  = sm + SM_CW;   float* wwn = sm + SM_WWN;
            float* red = sm + SM_RED;  float* scal= sm + SM_SCAL;
            int* irank = (int*)(sm + SM_IRANK);

            if (tid < IFACE) sv[tid] = g_v[b*480 + tid];
            __syncthreads();

            // parse interface
            if (tid < 64) ers[tid] = sigm(sv[325+tid]);
            if (tid < 4) {
                scal[4+tid] = 1.f + softplusf(sv[256+tid]);   // read beta
                scal[8+tid] = sigm(sv[453+tid]);              // free gate
                float m0=sv[459+3*tid], m1=sv[460+3*tid], m2=sv[461+3*tid];
                float mx=fmaxf(m0,fmaxf(m1,m2));
                float e0=expf(m0-mx), e1=expf(m1-mx), e2=expf(m2-mx);
                float si=e0+e1+e2;
                scal[16+3*tid]=e0/si; scal[17+3*tid]=e1/si; scal[18+3*tid]=e2/si;
                float s2=0.f;
                for (int w=0;w<64;w++){ float k=sv[tid*64+w]; s2+=k*k; }
                scal[12+tid]=sqrtf(s2)+EPSF;                  // ||read key||
            }
            if (tid == 4) {
                scal[0] = 1.f + softplusf(sv[324]);           // write beta
                float s2=0.f;
                for (int w=0;w<64;w++){ float k=sv[260+w]; s2+=k*k; }
                scal[3] = sqrtf(s2)+EPSF;                     // ||write key||
            }
            if (tid == 5) scal[1] = sigm(sv[457]);            // alloc gate
            if (tid == 6) scal[2] = sigm(sv[458]);            // write gate
            __syncthreads();

            // usage + write-content logits (old M, old wr, old ww)
            if (tid < 128) {
                float ret = 1.f;
                #pragma unroll
                for (int r=0;r<4;r++) ret *= (1.f - scal[8+r]*sWr[r*128+tid]);
                float uo = sU[tid], wwo = sW2[tid];
                float un = (uo + wwo - uo*wwo)*ret;
                u_s[tid] = un; sU[tid] = un;
                float d=0.f, n2=0.f;
                for (int w=0;w<64;w++){ float m=sM[tid*65+w]; d+=m*sv[260+w]; n2+=m*m; }
                cw[tid] = scal[0]*(d/((sqrtf(n2)+EPSF)*scal[3]));
                red[tid] = cw[tid];
            }
            __syncthreads();
            for (int st=64; st>=1; st>>=1){ if (tid<st) red[tid]=fmaxf(red[tid],red[tid+st]); __syncthreads(); }
            float wcmax = red[0]; __syncthreads();
            if (tid < 128) { float e=expf(cw[tid]-wcmax); cw[tid]=e; red[tid]=e; }
            __syncthreads();
            for (int st=64; st>=1; st>>=1){ if (tid<st) red[tid]+=red[tid+st]; __syncthreads(); }
            float wcsum = red[0]; __syncthreads();
            if (tid < 128) cw[tid] /= wcsum;

            // allocation: stable rank + cumprod scan
            if (tid < 128) {
                float un = u_s[tid]; int rk = 0;
                for (int m=0;m<128;m++){
                    float um = u_s[m];
                    rk += ((um<un) || (um==un && m<tid)) ? 1 : 0;
                }
                irank[tid]=rk; so[rk]=un; su[rk]=un;
            }
            __syncthreads();
            for (int d=1; d<128; d<<=1) {
                float tv = 1.f;
                if (tid < 128 && tid >= d) tv = so[tid-d];
                __syncthreads();
                if (tid < 128) so[tid] *= tv;
                __syncthreads();
            }
            if (tid < 128) {
                float cpe = (tid==0) ? 1.f : so[tid-1];
                a_s[tid] = (1.f - su[tid])*cpe;
            }
            __syncthreads();
            if (tid < 128) {
                float a = a_s[irank[tid]];
                float w = scal[2]*(scal[1]*a + (1.f-scal[1])*cw[tid]);
                wwn[tid] = w; sW2[tid] = w; red[tid] = w;
            }
            __syncthreads();
            for (int st=64; st>=1; st>>=1){ if (tid<st) red[tid]+=red[tid+st]; __syncthreads(); }
            float wwsum = red[0]; __syncthreads();

            // M update + link update (independent regions)
            for (int idx = tid; idx < 8192; idx += NTHR) {
                int n = idx>>6, w = idx&63;
                float m = sM[n*65+w];
                sM[n*65+w] = m*(1.f - wwn[n]*ers[w]) + wwn[n]*sv[389+w];
            }
            {
                int i = tid>>2, j0 = (tid&3)*32;
                float wwi = wwn[i];
                #pragma unroll 8
                for (int j = j0; j < j0+32; j++) {
                    float l = sL[i*129+j];
                    l = (1.f - wwi - wwn[j])*l + wwi*sP[j];
                    if (j == i) l = 0.f;
                    sL[i*129+j] = l;
                }
            }
            __syncthreads();
            if (tid < 128) sP[tid] = (1.f - wwsum)*sP[tid] + wwn[tid];
            // fw/bw (new link, old wr)
            {
                int r = tid>>7, i = tid&127;
                float f=0.f, bk=0.f;
                #pragma unroll 4
                for (int j=0;j<128;j++){
                    float wrj = sWr[r*128+j];
                    f  += sL[i*129+j]*wrj;
                    bk += sL[j*129+i]*wrj;
                }
                fwv[r*128+i]=f; bwv[r*128+i]=bk;
            }
            // read-content logits (new M)
            {
                int r = tid>>7, n = tid&127;
                float d=0.f, n2=0.f;
                for (int w=0;w<64;w++){ float m=sM[n*65+w]; d+=m*sv[r*64+w]; n2+=m*m; }
                crs[r*128+n] = scal[4+r]*d/((sqrtf(n2)+EPSF)*scal[12+r]);
                red[r*128+n] = crs[r*128+n];
            }
            __syncthreads();
            // 4-head parallel softmax
            {
                int r = tid>>7, n = tid&127;
                for (int st=64; st>=1; st>>=1){
                    if (n < st) red[r*128+n] = fmaxf(red[r*128+n], red[r*128+n+st]);
                    __syncthreads();
                }
                float mx = red[r*128];
                __syncthreads();
                float e = expf(crs[r*128+n]-mx);
                crs[r*128+n] = e; red[r*128+n] = e;
                __syncthreads();
                for (int st=64; st>=1; st>>=1){
                    if (n < st) red[r*128+n] += red[r*128+n+st];
                    __syncthreads();
                }
                float ssum = red[r*128];
                float cc = e/ssum;
                float w = scal[16+3*r]*bwv[r*128+n] + scal[17+3*r]*cc + scal[18+3*r]*fwv[r*128+n];
                wrn[r*128+n] = w; sWr[r*128+n] = w;
            }
            __syncthreads();
            // reads
            if (tid < 256) {
                int r = tid>>6, w = tid&63;
                float sr = 0.f;
                #pragma unroll 4
                for (int n=0;n<128;n++) sr += wrn[r*128+n]*sM[n*65+w];
                g_reads[b*256 + tid] = sr;
            }
        }
        gsync();
    }

    // final out(127): h(127) is in g_h[0], g_reads holds reads(127)
    out_gemm(Wout, bout, out, g_h[0], 127, bq, tid, stg, zb);
}

extern "C" void kernel_launch(void* const* d_in, const int* in_sizes, int n_in,
                              void* d_out, int out_size)
{
    const float* xseq = (const float*)d_in[0];
    const float* Wx   = (const float*)d_in[1];
    const float* Wh   = (const float*)d_in[2];
    const float* bl   = (const float*)d_in[3];
    const float* Wif  = (const float*)d_in[4];
    const float* bif  = (const float*)d_in[5];
    const float* Wout = (const float*)d_in[6];
    const float* bout = (const float*)d_in[7];
    float* out = (float*)d_out;

    cudaFuncSetAttribute(dnc_kernel, cudaFuncAttributeMaxDynamicSharedMemorySize, SMEM_BYTES);
    dnc_kernel<<<NBLK, NTHR, SMEM_BYTES>>>(xseq, Wx, Wh, bl, Wif, bif, Wout, bout, out);
}